// round 11
// baseline (speedup 1.0000x reference)
#include <cuda_runtime.h>
#include <math.h>

// Problem constants (fixed shapes per reference setup_inputs)
#define NB    2
#define NDIM  128          // D = H = W = 128
#define NC    4            // image channels
#define IMG_ELEMS (NB * NDIM * NDIM * NDIM * NC)   // 16777216

// Combined (Gauss o cubic-resize) 128x4 per-axis weights, Dekker hi/lo f32
// pairs split from the f64 values (value = hi + lo to ~2^-48 relative).
__device__ float Mhi_g[NDIM][4];
__device__ float Mlo_g[NDIM][4];
// T2[b][d][h][k*3+c] = sum_{i,j} M[d][i] M[h][j] coarse[b][i][j][k][c],
// computed in f64, stored as hi/lo f32 pairs.
__device__ float T2hi_g[NB][NDIM][NDIM][12];
__device__ float T2lo_g[NB][NDIM][NDIM][12];

// ---------------------------------------------------------------------------
// Build kernel: per block (d, b), 128 threads over h.
//  1. f32-quantized cubic-resize rows Rs[128][4] and Gaussian taps Gf[16]
//     (f64 compute -> f32 cast, matching jax weight quantization).
//  2. Mh rows composed in f64 from the f32 factors; Md read from shared.
//  3. T2 contraction factored: S[j][kc] = sum_i Md[i]*C[i][j][kc] (shared,
//     48 threads x 4 DFMA), then per-thread sum_j Mh[j]*S[j][kc] (48 DFMA).
//  4. Store T2 hi/lo; block (0,0) publishes M hi/lo.
// ---------------------------------------------------------------------------
__global__ void build_T2_kernel(const float* __restrict__ coarse) {
    const int d = blockIdx.x;
    const int b = blockIdx.y;
    const int h = threadIdx.x;

    __shared__ float  Rs[NDIM][4];   // f32-quantized resize weights
    __shared__ double GrRaw[16];
    __shared__ float  Gf[16];        // f32-quantized gaussian taps
    __shared__ double Cs[192];       // coarse flow for this batch (f64)
    __shared__ double Msh[NDIM][4];  // f64 M rows (index = axis coord)
    __shared__ double S[48];         // i-contracted stage [j][k*3+c]

    // --- cubic resize row h: sample position (h+0.5)/32 - 0.5, input size 4
    {
        double s = (h + 0.5) / 32.0 - 0.5;
        double w[4];
        double sum = 0.0;
        #pragma unroll
        for (int j = 0; j < 4; j++) {
            double x = fabs(s - (double)j);
            double v;
            if (x < 1.0)       v = ((1.5 * x - 2.5) * x) * x + 1.0;
            else if (x < 2.0)  v = ((-0.5 * x + 2.5) * x - 4.0) * x + 2.0;
            else               v = 0.0;
            w[j] = v;
            sum += v;
        }
        #pragma unroll
        for (int j = 0; j < 4; j++) Rs[h][j] = (float)(w[j] / sum);
    }

    // --- Gaussian raw taps (one exp per thread h<16)
    if (h < 16) {
        double a = (double)(h - 7);
        GrRaw[h] = exp(-a * a / (2.0 * 2.5 * 2.5));
    }
    // --- coarse flow into shared (f64)
    for (int i = h; i < 192; i += blockDim.x) Cs[i] = (double)coarse[b * 192 + i];
    __syncthreads();

    if (h < 16) {
        double gs = 0.0;
        #pragma unroll
        for (int t = 0; t < 16; t++) gs += GrRaw[t];
        Gf[h] = (float)(GrRaw[h] / gs);
    }
    __syncthreads();

    // --- compose M row h in f64: M[h][j] = sum_t Gf[t] * Rs[h+t-7][j]
    double Mh[4];
    #pragma unroll
    for (int j = 0; j < 4; j++) Mh[j] = 0.0;
    #pragma unroll
    for (int t = 0; t < 16; t++) {
        const int sh = h + t - 7;
        if (sh >= 0 && sh < NDIM) {
            const double g = (double)Gf[t];
            #pragma unroll
            for (int j = 0; j < 4; j++) Mh[j] += g * (double)Rs[sh][j];
        }
    }
    #pragma unroll
    for (int j = 0; j < 4; j++) Msh[h][j] = Mh[j];

    if (d == 0 && b == 0) {
        #pragma unroll
        for (int j = 0; j < 4; j++) {
            float hi = (float)Mh[j];
            Mhi_g[h][j] = hi;
            Mlo_g[h][j] = (float)(Mh[j] - (double)hi);
        }
    }
    __syncthreads();

    // --- stage 1: S[j*12+kc] = sum_i Md[i] * Cs[(i*4+j)*12 + kc]
    if (h < 48) {
        const int j  = h / 12;
        const int kc = h % 12;
        double acc = 0.0;
        #pragma unroll
        for (int i = 0; i < 4; i++)
            acc = fma(Msh[d][i], Cs[(i * 4 + j) * 12 + kc], acc);
        S[h] = acc;
    }
    __syncthreads();

    // --- stage 2: T2[kc] = sum_j Mh[j] * S[j*12+kc]; store hi/lo
    #pragma unroll
    for (int kc = 0; kc < 12; kc++) {
        double a = Mh[0] * S[kc] + Mh[1] * S[12 + kc]
                 + Mh[2] * S[24 + kc] + Mh[3] * S[36 + kc];
        float hi = (float)a;
        T2hi_g[b][d][h][kc] = hi;
        T2lo_g[b][d][h][kc] = (float)(a - (double)hi);
    }
}

// ---------------------------------------------------------------------------
// Main warp kernel. One thread per output voxel (b,d,h,w).
// block = (128, 2) -> w = tx, h = 2*blockIdx.x + ty; grid = (64, 128, 2).
// Flow dot computed entirely in f32 via error-free transforms (TwoProd +
// cross terms + TwoSum compensation) on hi/lo pairs — no fp64 in this
// kernel. Result is the correctly-rounded f32 flow to ~2^-45 relative,
// then the exact reference f32 roundings: *35 (rn mul), +grid (rn add).
// Trilinear image sample (8 float4 gathers), nearest label.
// ---------------------------------------------------------------------------
__global__ __launch_bounds__(256) void warp_kernel(
    const float4* __restrict__ img,   // [B,D,H,W] of float4 (C=4)
    const int*    __restrict__ lab,   // [B,D,H,W]
    float*        __restrict__ out)   // image (float4) then label floats
{
    const int w  = threadIdx.x;
    const int ty = threadIdx.y;
    const int h  = (blockIdx.x << 1) + ty;
    const int d  = blockIdx.y;
    const int b  = blockIdx.z;

    __shared__ float t2s[2][24];      // [ty][0..11]=hi, [12..23]=lo
    if (w < 12)       t2s[ty][w]      = T2hi_g[b][d][h][w];
    else if (w < 24)  t2s[ty][w]      = T2lo_g[b][d][h][w - 12];
    __syncthreads();

    const float4 mh4 = *reinterpret_cast<const float4*>(&Mhi_g[w][0]);
    const float4 ml4 = *reinterpret_cast<const float4*>(&Mlo_g[w][0]);
    const float mhi[4] = { mh4.x, mh4.y, mh4.z, mh4.w };
    const float mlo[4] = { ml4.x, ml4.y, ml4.z, ml4.w };

    float flow[3];
    #pragma unroll
    for (int c = 0; c < 3; c++) {
        float s = 0.0f, comp = 0.0f;
        #pragma unroll
        for (int k = 0; k < 4; k++) {
            const float th = t2s[ty][k * 3 + c];
            const float tl = t2s[ty][12 + k * 3 + c];
            // TwoProd + cross terms: p + e = mhi*th + mhi*tl + mlo*th
            float p = __fmul_rn(mhi[k], th);
            float e = fmaf(mhi[k], th, -p);
            e = fmaf(mhi[k], tl, e);
            e = fmaf(mlo[k], th, e);
            // branch-free TwoSum(s, p)
            float sn = __fadd_rn(s, p);
            float z  = __fsub_rn(sn, s);
            float serr = __fadd_rn(__fsub_rn(s, __fsub_rn(sn, z)),
                                   __fsub_rn(p, z));
            s = sn;
            comp = __fadd_rn(comp, __fadd_rn(serr, e));
        }
        flow[c] = __fadd_rn(s, comp);
    }

    // Replicate reference f32 roundings: flow(f32) -> *35 (f32) -> +grid (f32)
    const float wd = __fadd_rn((float)d, __fmul_rn(35.0f, flow[0]));
    const float wh = __fadd_rn((float)h, __fmul_rn(35.0f, flow[1]));
    const float ww = __fadd_rn((float)w, __fmul_rn(35.0f, flow[2]));

    const float fdf = floorf(wd), fhf = floorf(wh), fwf = floorf(ww);
    const float td = wd - fdf, th_ = wh - fhf, tw = ww - fwf;

    const int d0 = min(max((int)fdf, 0), NDIM - 1);
    const int h0 = min(max((int)fhf, 0), NDIM - 1);
    const int w0 = min(max((int)fwf, 0), NDIM - 1);
    const int d1 = min(max((int)fdf + 1, 0), NDIM - 1);
    const int h1 = min(max((int)fhf + 1, 0), NDIM - 1);
    const int w1 = min(max((int)fwf + 1, 0), NDIM - 1);

    const int bb = b * NDIM;
    #define VIDX(di, hi, wi) ((((bb + (di)) * NDIM + (hi)) * NDIM) + (wi))

    // nearest-neighbor label gather issued first to overlap
    const int nd = min(max((int)rintf(wd), 0), NDIM - 1);
    const int nh = min(max((int)rintf(wh), 0), NDIM - 1);
    const int nw = min(max((int)rintf(ww), 0), NDIM - 1);
    const int lv = __ldg(&lab[VIDX(nd, nh, nw)]);

    const float4 v000 = __ldg(&img[VIDX(d0, h0, w0)]);
    const float4 v001 = __ldg(&img[VIDX(d0, h0, w1)]);
    const float4 v010 = __ldg(&img[VIDX(d0, h1, w0)]);
    const float4 v011 = __ldg(&img[VIDX(d0, h1, w1)]);
    const float4 v100 = __ldg(&img[VIDX(d1, h0, w0)]);
    const float4 v101 = __ldg(&img[VIDX(d1, h0, w1)]);
    const float4 v110 = __ldg(&img[VIDX(d1, h1, w0)]);
    const float4 v111 = __ldg(&img[VIDX(d1, h1, w1)]);

    const float omw = 1.0f - tw, omh = 1.0f - th_, omd = 1.0f - td;

    float4 c00, c01, c10, c11, c0, c1, res;
    c00.x = v000.x * omw + v001.x * tw;  c00.y = v000.y * omw + v001.y * tw;
    c00.z = v000.z * omw + v001.z * tw;  c00.w = v000.w * omw + v001.w * tw;
    c01.x = v010.x * omw + v011.x * tw;  c01.y = v010.y * omw + v011.y * tw;
    c01.z = v010.z * omw + v011.z * tw;  c01.w = v010.w * omw + v011.w * tw;
    c10.x = v100.x * omw + v101.x * tw;  c10.y = v100.y * omw + v101.y * tw;
    c10.z = v100.z * omw + v101.z * tw;  c10.w = v100.w * omw + v101.w * tw;
    c11.x = v110.x * omw + v111.x * tw;  c11.y = v110.y * omw + v111.y * tw;
    c11.z = v110.z * omw + v111.z * tw;  c11.w = v110.w * omw + v111.w * tw;

    c0.x = c00.x * omh + c01.x * th_;  c0.y = c00.y * omh + c01.y * th_;
    c0.z = c00.z * omh + c01.z * th_;  c0.w = c00.w * omh + c01.w * th_;
    c1.x = c10.x * omh + c11.x * th_;  c1.y = c10.y * omh + c11.y * th_;
    c1.z = c10.z * omh + c11.z * th_;  c1.w = c10.w * omh + c11.w * th_;

    res.x = c0.x * omd + c1.x * td;  res.y = c0.y * omd + c1.y * td;
    res.z = c0.z * omd + c1.z * td;  res.w = c0.w * omd + c1.w * td;

    const int lin = VIDX(d, h, w);
    reinterpret_cast<float4*>(out)[lin] = res;
    out[IMG_ELEMS + lin] = (float)lv;
    #undef VIDX
}

// ---------------------------------------------------------------------------
// kernel_launch — graph-capturable, allocation-free
// ---------------------------------------------------------------------------
extern "C" void kernel_launch(void* const* d_in, const int* in_sizes, int n_in,
                              void* d_out, int out_size) {
    const float4* img    = (const float4*)d_in[0];  // image_volume [2,128,128,128,4] f32
    const int*    lab    = (const int*)d_in[1];     // label_volume [2,128,128,128,1] i32
    const float*  coarse = (const float*)d_in[2];   // coarse_flow  [2,4,4,4,3] f32
    float*        out    = (float*)d_out;

    build_T2_kernel<<<dim3(NDIM, NB), NDIM>>>(coarse);
    warp_kernel<<<dim3(NDIM / 2, NDIM, NB), dim3(NDIM, 2)>>>(img, lab, out);
}

// round 14
// speedup vs baseline: 1.6859x; 1.6859x over previous
#include <cuda_runtime.h>
#include <math.h>

// Problem constants (fixed shapes per reference setup_inputs)
#define NB    2
#define NDIM  128          // D = H = W = 128
#define NC    4            // image channels
#define IMG_ELEMS (NB * NDIM * NDIM * NDIM * NC)   // 16777216

// Combined (Gauss o cubic-resize) 128x4 per-axis weights.
__device__ double Mgd[NDIM][4];    // f64 master copy
__device__ float  Mhi_g[NDIM][4];  // Dekker hi
__device__ float  Mlo_g[NDIM][4];  // Dekker lo
// T2 packed per (b,d,h): [0..11] = hi, [12..23] = lo  (kc = k*3 + c)
__device__ float  T2p[NB][NDIM][NDIM][24];

// ---------------------------------------------------------------------------
// Kernel A: build M = G @ R once. 1 block, 128 threads, exactly 16 f64 exps
// total (one per tap thread). R and G quantized to f32 (matching jax's
// f64-compute -> f32-cast weights), composed in f64, published f64 + hi/lo.
// ---------------------------------------------------------------------------
__global__ void build_M_kernel() {
    __shared__ float  Rs[NDIM][4];
    __shared__ double GrRaw[16];
    __shared__ float  Gf[16];
    const int h = threadIdx.x;

    // cubic resize row h (Keys a=-0.5, signed-sum renormalized), f64 -> f32
    {
        double s = (h + 0.5) / 32.0 - 0.5;
        double w[4];
        double sum = 0.0;
        #pragma unroll
        for (int j = 0; j < 4; j++) {
            double x = fabs(s - (double)j);
            double v;
            if (x < 1.0)       v = ((1.5 * x - 2.5) * x) * x + 1.0;
            else if (x < 2.0)  v = ((-0.5 * x + 2.5) * x - 4.0) * x + 2.0;
            else               v = 0.0;
            w[j] = v;
            sum += v;
        }
        #pragma unroll
        for (int j = 0; j < 4; j++) Rs[h][j] = (float)(w[j] / sum);
    }

    // Gaussian: ONE exp per tap thread
    if (h < 16) {
        double a = (double)(h - 7);
        GrRaw[h] = exp(-a * a / (2.0 * 2.5 * 2.5));
    }
    __syncthreads();
    if (h < 16) {
        double gs = 0.0;
        #pragma unroll
        for (int t = 0; t < 16; t++) gs += GrRaw[t];
        Gf[h] = (float)(GrRaw[h] / gs);
    }
    __syncthreads();

    // M[h][j] = sum_t Gf[t] * Rs[h+t-7][j], zero-padded SAME
    double Mh[4] = {0.0, 0.0, 0.0, 0.0};
    #pragma unroll
    for (int t = 0; t < 16; t++) {
        const int sh = h + t - 7;
        if (sh >= 0 && sh < NDIM) {
            const double g = (double)Gf[t];
            #pragma unroll
            for (int j = 0; j < 4; j++) Mh[j] += g * (double)Rs[sh][j];
        }
    }
    #pragma unroll
    for (int j = 0; j < 4; j++) {
        Mgd[h][j] = Mh[j];
        float hi = (float)Mh[j];
        Mhi_g[h][j] = hi;
        Mlo_g[h][j] = (float)(Mh[j] - (double)hi);
    }
}

// ---------------------------------------------------------------------------
// Kernel B: T2 contraction only (M read from global). Per block (d, b),
// 128 threads over h. Staged: S[j][kc] = sum_i Md[i]*C[i][j][kc] (48 thr x
// 4 DFMA), then per-thread sum_j Mh[j]*S[j][kc] (48 DFMA). Stores hi/lo.
// ---------------------------------------------------------------------------
__global__ void build_T2_kernel(const float* __restrict__ coarse) {
    const int d = blockIdx.x;
    const int b = blockIdx.y;
    const int h = threadIdx.x;

    __shared__ double Cs[192];
    __shared__ double S[48];

    for (int i = h; i < 192; i += blockDim.x) Cs[i] = (double)coarse[b * 192 + i];
    __syncthreads();

    if (h < 48) {
        const int j  = h / 12;
        const int kc = h % 12;
        double acc = 0.0;
        #pragma unroll
        for (int i = 0; i < 4; i++)
            acc = fma(Mgd[d][i], Cs[(i * 4 + j) * 12 + kc], acc);
        S[h] = acc;
    }
    __syncthreads();

    const double m0 = Mgd[h][0], m1 = Mgd[h][1], m2 = Mgd[h][2], m3 = Mgd[h][3];
    #pragma unroll
    for (int kc = 0; kc < 12; kc++) {
        double a = m0 * S[kc] + m1 * S[12 + kc] + m2 * S[24 + kc] + m3 * S[36 + kc];
        float hi = (float)a;
        T2p[b][d][h][kc]      = hi;
        T2p[b][d][h][12 + kc] = (float)(a - (double)hi);
    }
}

// branch-free TwoSum: s + err == a + b exactly
__device__ __forceinline__ void two_sum(float a, float b, float& s, float& err) {
    s = __fadd_rn(a, b);
    float z = __fsub_rn(s, a);
    err = __fadd_rn(__fsub_rn(a, __fsub_rn(s, z)), __fsub_rn(b, z));
}

// ---------------------------------------------------------------------------
// Kernel C: main warp. One thread per voxel (b,d,h,w). No shared memory, no
// barriers. T2 hi/lo via 6 uniform float4 LDGs (warp broadcast); M hi/lo via
// 2 coalesced float4 LDGs. Flow dot via error-free f32 transforms with a
// pairwise (shallow) TwoSum tree — reproduces the f64 flow to ~2^-45, then
// the exact reference f32 roundings: *35 (rn mul), +grid (rn add).
// ---------------------------------------------------------------------------
__global__ __launch_bounds__(256) void warp_kernel(
    const float4* __restrict__ img,   // [B,D,H,W] of float4 (C=4)
    const int*    __restrict__ lab,   // [B,D,H,W]
    float*        __restrict__ out)   // image (float4) then label floats
{
    const int w = threadIdx.x;
    const int h = (blockIdx.x << 1) + threadIdx.y;
    const int d = blockIdx.y;
    const int b = blockIdx.z;

    // T2 row: 24 floats = 6 float4, uniform across the warp (broadcast)
    const float4* t2q = reinterpret_cast<const float4*>(&T2p[b][d][h][0]);
    const float4 q0 = __ldg(&t2q[0]), q1 = __ldg(&t2q[1]), q2 = __ldg(&t2q[2]);
    const float4 q3 = __ldg(&t2q[3]), q4 = __ldg(&t2q[4]), q5 = __ldg(&t2q[5]);
    const float t2h[12] = { q0.x, q0.y, q0.z, q0.w, q1.x, q1.y, q1.z, q1.w,
                            q2.x, q2.y, q2.z, q2.w };
    const float t2l[12] = { q3.x, q3.y, q3.z, q3.w, q4.x, q4.y, q4.z, q4.w,
                            q5.x, q5.y, q5.z, q5.w };

    const float4 mh4 = __ldg(reinterpret_cast<const float4*>(&Mhi_g[w][0]));
    const float4 ml4 = __ldg(reinterpret_cast<const float4*>(&Mlo_g[w][0]));
    const float mhi[4] = { mh4.x, mh4.y, mh4.z, mh4.w };
    const float mlo[4] = { ml4.x, ml4.y, ml4.z, ml4.w };

    float flow[3];
    #pragma unroll
    for (int c = 0; c < 3; c++) {
        // products + full residuals (independent, shallow)
        float p[4], e[4];
        #pragma unroll
        for (int k = 0; k < 4; k++) {
            const float th = t2h[k * 3 + c];
            p[k] = __fmul_rn(mhi[k], th);
            float r = fmaf(mhi[k], th, -p[k]);           // exact TwoProd residual
            r = fmaf(mhi[k], t2l[k * 3 + c], r);         // hi*lo cross
            e[k] = fmaf(mlo[k], th, r);                  // lo*hi cross
        }
        // pairwise TwoSum tree (depth 2)
        float s01, e01, s23, e23, s, es;
        two_sum(p[0], p[1], s01, e01);
        two_sum(p[2], p[3], s23, e23);
        two_sum(s01, s23, s, es);
        const float corr = __fadd_rn(__fadd_rn(__fadd_rn(e01, e23), es),
                                     __fadd_rn(__fadd_rn(e[0], e[1]),
                                               __fadd_rn(e[2], e[3])));
        flow[c] = __fadd_rn(s, corr);
    }

    // Replicate reference f32 roundings: flow(f32) -> *35 (f32) -> +grid (f32)
    const float wd = __fadd_rn((float)d, __fmul_rn(35.0f, flow[0]));
    const float wh = __fadd_rn((float)h, __fmul_rn(35.0f, flow[1]));
    const float ww = __fadd_rn((float)w, __fmul_rn(35.0f, flow[2]));

    const float fdf = floorf(wd), fhf = floorf(wh), fwf = floorf(ww);
    const float td = wd - fdf, th_ = wh - fhf, tw = ww - fwf;

    const int d0 = min(max((int)fdf, 0), NDIM - 1);
    const int h0 = min(max((int)fhf, 0), NDIM - 1);
    const int w0 = min(max((int)fwf, 0), NDIM - 1);
    const int d1 = min(max((int)fdf + 1, 0), NDIM - 1);
    const int h1 = min(max((int)fhf + 1, 0), NDIM - 1);
    const int w1 = min(max((int)fwf + 1, 0), NDIM - 1);

    const int bb = b * NDIM;
    #define VIDX(di, hi, wi) ((((bb + (di)) * NDIM + (hi)) * NDIM) + (wi))

    // nearest-neighbor label gather issued first to overlap
    const int nd = min(max((int)rintf(wd), 0), NDIM - 1);
    const int nh = min(max((int)rintf(wh), 0), NDIM - 1);
    const int nw = min(max((int)rintf(ww), 0), NDIM - 1);
    const int lv = __ldg(&lab[VIDX(nd, nh, nw)]);

    const float4 v000 = __ldg(&img[VIDX(d0, h0, w0)]);
    const float4 v001 = __ldg(&img[VIDX(d0, h0, w1)]);
    const float4 v010 = __ldg(&img[VIDX(d0, h1, w0)]);
    const float4 v011 = __ldg(&img[VIDX(d0, h1, w1)]);
    const float4 v100 = __ldg(&img[VIDX(d1, h0, w0)]);
    const float4 v101 = __ldg(&img[VIDX(d1, h0, w1)]);
    const float4 v110 = __ldg(&img[VIDX(d1, h1, w0)]);
    const float4 v111 = __ldg(&img[VIDX(d1, h1, w1)]);

    const float omw = 1.0f - tw, omh = 1.0f - th_, omd = 1.0f - td;

    float4 c00, c01, c10, c11, c0, c1, res;
    c00.x = v000.x * omw + v001.x * tw;  c00.y = v000.y * omw + v001.y * tw;
    c00.z = v000.z * omw + v001.z * tw;  c00.w = v000.w * omw + v001.w * tw;
    c01.x = v010.x * omw + v011.x * tw;  c01.y = v010.y * omw + v011.y * tw;
    c01.z = v010.z * omw + v011.z * tw;  c01.w = v010.w * omw + v011.w * tw;
    c10.x = v100.x * omw + v101.x * tw;  c10.y = v100.y * omw + v101.y * tw;
    c10.z = v100.z * omw + v101.z * tw;  c10.w = v100.w * omw + v101.w * tw;
    c11.x = v110.x * omw + v111.x * tw;  c11.y = v110.y * omw + v111.y * tw;
    c11.z = v110.z * omw + v111.z * tw;  c11.w = v110.w * omw + v111.w * tw;

    c0.x = c00.x * omh + c01.x * th_;  c0.y = c00.y * omh + c01.y * th_;
    c0.z = c00.z * omh + c01.z * th_;  c0.w = c00.w * omh + c01.w * th_;
    c1.x = c10.x * omh + c11.x * th_;  c1.y = c10.y * omh + c11.y * th_;
    c1.z = c10.z * omh + c11.z * th_;  c1.w = c10.w * omh + c11.w * th_;

    res.x = c0.x * omd + c1.x * td;  res.y = c0.y * omd + c1.y * td;
    res.z = c0.z * omd + c1.z * td;  res.w = c0.w * omd + c1.w * td;

    const int lin = VIDX(d, h, w);
    reinterpret_cast<float4*>(out)[lin] = res;
    out[IMG_ELEMS + lin] = (float)lv;
    #undef VIDX
}

// ---------------------------------------------------------------------------
// kernel_launch — graph-capturable, allocation-free
// ---------------------------------------------------------------------------
extern "C" void kernel_launch(void* const* d_in, const int* in_sizes, int n_in,
                              void* d_out, int out_size) {
    const float4* img    = (const float4*)d_in[0];  // image_volume [2,128,128,128,4] f32
    const int*    lab    = (const int*)d_in[1];     // label_volume [2,128,128,128,1] i32
    const float*  coarse = (const float*)d_in[2];   // coarse_flow  [2,4,4,4,3] f32
    float*        out    = (float*)d_out;

    build_M_kernel<<<1, NDIM>>>();
    build_T2_kernel<<<dim3(NDIM, NB), NDIM>>>(coarse);
    warp_kernel<<<dim3(NDIM / 2, NDIM, NB), dim3(NDIM, 2)>>>(img, lab, out);
}

// round 15
// speedup vs baseline: 1.7921x; 1.0630x over previous
#include <cuda_runtime.h>
#include <math.h>

// Problem constants (fixed shapes per reference setup_inputs)
#define NB    2
#define NDIM  128          // D = H = W = 128
#define NC    4            // image channels
#define IMG_ELEMS (NB * NDIM * NDIM * NDIM * NC)   // 16777216

// Combined (Gauss o cubic-resize) 128x4 per-axis weights.
__device__ double Mgd[NDIM][4];    // f64 master copy
__device__ float  Mhi_g[NDIM][4];  // Dekker hi
__device__ float  Mlo_g[NDIM][4];  // Dekker lo
// T2 packed per (b,d,h): [0..11] = hi, [12..23] = lo  (kc = k*3 + c)
__device__ float  T2p[NB][NDIM][NDIM][24];

// ---------------------------------------------------------------------------
// Kernel A: build M = G @ R, parallelized: 128 blocks (one per row h),
// 64 threads = 16 taps (t) x 4 columns (j). Per thread: one f64 exp, one
// f64 cubic-row eval, one DMUL; width-16 shuffle-tree reductions.
// R and G quantized to f32 (matching jax's f64-compute -> f32-cast weights),
// composed in f64, published f64 + Dekker hi/lo f32.
// ---------------------------------------------------------------------------
__global__ void build_M_kernel() {
    const int tid = threadIdx.x;
    const int t   = tid & 15;     // gaussian tap 0..15  (offset t-7)
    const int j   = tid >> 4;     // resize column 0..3
    const int h   = blockIdx.x;   // output row

    // --- Gaussian tap t: one exp per thread; group-sum for normalizer
    const double a = (double)(t - 7);
    const double graw = exp(-a * a / (2.0 * 2.5 * 2.5));
    double gs = graw;
    #pragma unroll
    for (int off = 8; off >= 1; off >>= 1)
        gs += __shfl_down_sync(0xFFFFFFFFu, gs, off, 16);
    gs = __shfl_sync(0xFFFFFFFFu, gs, 0, 16);        // broadcast within group
    const float gf = (float)(graw / gs);             // f32-quantized tap

    // --- cubic resize row src = h + t - 7 (Keys a=-0.5, signed-sum renorm)
    const int src = h + t - 7;
    float rs = 0.0f;
    if (src >= 0 && src < NDIM) {
        double s = (src + 0.5) / 32.0 - 0.5;
        double w[4];
        double sum = 0.0;
        #pragma unroll
        for (int jj = 0; jj < 4; jj++) {
            double x = fabs(s - (double)jj);
            double v;
            if (x < 1.0)       v = ((1.5 * x - 2.5) * x) * x + 1.0;
            else if (x < 2.0)  v = ((-0.5 * x + 2.5) * x - 4.0) * x + 2.0;
            else               v = 0.0;
            w[jj] = v;
            sum += v;
        }
        rs = (float)(w[j] / sum);                    // f32-quantized weight
    }

    // --- partial product and tap-reduction: M[h][j] = sum_t gf_t * rs_t
    double part = (double)gf * (double)rs;
    #pragma unroll
    for (int off = 8; off >= 1; off >>= 1)
        part += __shfl_down_sync(0xFFFFFFFFu, part, off, 16);

    if (t == 0) {
        Mgd[h][j] = part;
        float hi = (float)part;
        Mhi_g[h][j] = hi;
        Mlo_g[h][j] = (float)(part - (double)hi);
    }
}

// ---------------------------------------------------------------------------
// Kernel B: T2 contraction only (M read from global). Per block (d, b),
// 128 threads over h. Staged: S[j][kc] = sum_i Md[i]*C[i][j][kc] (48 thr x
// 4 DFMA), then per-thread sum_j Mh[j]*S[j][kc] (48 DFMA). Stores hi/lo.
// ---------------------------------------------------------------------------
__global__ void build_T2_kernel(const float* __restrict__ coarse) {
    const int d = blockIdx.x;
    const int b = blockIdx.y;
    const int h = threadIdx.x;

    __shared__ double Cs[192];
    __shared__ double S[48];

    for (int i = h; i < 192; i += blockDim.x) Cs[i] = (double)coarse[b * 192 + i];
    __syncthreads();

    if (h < 48) {
        const int j  = h / 12;
        const int kc = h % 12;
        double acc = 0.0;
        #pragma unroll
        for (int i = 0; i < 4; i++)
            acc = fma(Mgd[d][i], Cs[(i * 4 + j) * 12 + kc], acc);
        S[h] = acc;
    }
    __syncthreads();

    const double m0 = Mgd[h][0], m1 = Mgd[h][1], m2 = Mgd[h][2], m3 = Mgd[h][3];
    #pragma unroll
    for (int kc = 0; kc < 12; kc++) {
        double a = m0 * S[kc] + m1 * S[12 + kc] + m2 * S[24 + kc] + m3 * S[36 + kc];
        float hi = (float)a;
        T2p[b][d][h][kc]      = hi;
        T2p[b][d][h][12 + kc] = (float)(a - (double)hi);
    }
}

// branch-free TwoSum: s + err == a + b exactly
__device__ __forceinline__ void two_sum(float a, float b, float& s, float& err) {
    s = __fadd_rn(a, b);
    float z = __fsub_rn(s, a);
    err = __fadd_rn(__fsub_rn(a, __fsub_rn(s, z)), __fsub_rn(b, z));
}

// ---------------------------------------------------------------------------
// Kernel C: main warp. One thread per voxel (b,d,h,w). No shared memory, no
// barriers. T2 hi/lo via 6 uniform float4 LDGs (warp broadcast); M hi/lo via
// 2 coalesced float4 LDGs. Flow dot via error-free f32 transforms with a
// pairwise (shallow) TwoSum tree — reproduces the f64 flow to ~2^-45, then
// the exact reference f32 roundings: *35 (rn mul), +grid (rn add).
// ---------------------------------------------------------------------------
__global__ __launch_bounds__(256) void warp_kernel(
    const float4* __restrict__ img,   // [B,D,H,W] of float4 (C=4)
    const int*    __restrict__ lab,   // [B,D,H,W]
    float*        __restrict__ out)   // image (float4) then label floats
{
    const int w = threadIdx.x;
    const int h = (blockIdx.x << 1) + threadIdx.y;
    const int d = blockIdx.y;
    const int b = blockIdx.z;

    // T2 row: 24 floats = 6 float4, uniform across the warp (broadcast)
    const float4* t2q = reinterpret_cast<const float4*>(&T2p[b][d][h][0]);
    const float4 q0 = __ldg(&t2q[0]), q1 = __ldg(&t2q[1]), q2 = __ldg(&t2q[2]);
    const float4 q3 = __ldg(&t2q[3]), q4 = __ldg(&t2q[4]), q5 = __ldg(&t2q[5]);
    const float t2h[12] = { q0.x, q0.y, q0.z, q0.w, q1.x, q1.y, q1.z, q1.w,
                            q2.x, q2.y, q2.z, q2.w };
    const float t2l[12] = { q3.x, q3.y, q3.z, q3.w, q4.x, q4.y, q4.z, q4.w,
                            q5.x, q5.y, q5.z, q5.w };

    const float4 mh4 = __ldg(reinterpret_cast<const float4*>(&Mhi_g[w][0]));
    const float4 ml4 = __ldg(reinterpret_cast<const float4*>(&Mlo_g[w][0]));
    const float mhi[4] = { mh4.x, mh4.y, mh4.z, mh4.w };
    const float mlo[4] = { ml4.x, ml4.y, ml4.z, ml4.w };

    float flow[3];
    #pragma unroll
    for (int c = 0; c < 3; c++) {
        // products + full residuals (independent, shallow)
        float p[4], e[4];
        #pragma unroll
        for (int k = 0; k < 4; k++) {
            const float th = t2h[k * 3 + c];
            p[k] = __fmul_rn(mhi[k], th);
            float r = fmaf(mhi[k], th, -p[k]);           // exact TwoProd residual
            r = fmaf(mhi[k], t2l[k * 3 + c], r);         // hi*lo cross
            e[k] = fmaf(mlo[k], th, r);                  // lo*hi cross
        }
        // pairwise TwoSum tree (depth 2)
        float s01, e01, s23, e23, s, es;
        two_sum(p[0], p[1], s01, e01);
        two_sum(p[2], p[3], s23, e23);
        two_sum(s01, s23, s, es);
        const float corr = __fadd_rn(__fadd_rn(__fadd_rn(e01, e23), es),
                                     __fadd_rn(__fadd_rn(e[0], e[1]),
                                               __fadd_rn(e[2], e[3])));
        flow[c] = __fadd_rn(s, corr);
    }

    // Replicate reference f32 roundings: flow(f32) -> *35 (f32) -> +grid (f32)
    const float wd = __fadd_rn((float)d, __fmul_rn(35.0f, flow[0]));
    const float wh = __fadd_rn((float)h, __fmul_rn(35.0f, flow[1]));
    const float ww = __fadd_rn((float)w, __fmul_rn(35.0f, flow[2]));

    const float fdf = floorf(wd), fhf = floorf(wh), fwf = floorf(ww);
    const float td = wd - fdf, th_ = wh - fhf, tw = ww - fwf;

    const int d0 = min(max((int)fdf, 0), NDIM - 1);
    const int h0 = min(max((int)fhf, 0), NDIM - 1);
    const int w0 = min(max((int)fwf, 0), NDIM - 1);
    const int d1 = min(max((int)fdf + 1, 0), NDIM - 1);
    const int h1 = min(max((int)fhf + 1, 0), NDIM - 1);
    const int w1 = min(max((int)fwf + 1, 0), NDIM - 1);

    const int bb = b * NDIM;
    #define VIDX(di, hi, wi) ((((bb + (di)) * NDIM + (hi)) * NDIM) + (wi))

    // nearest-neighbor label gather issued first to overlap
    const int nd = min(max((int)rintf(wd), 0), NDIM - 1);
    const int nh = min(max((int)rintf(wh), 0), NDIM - 1);
    const int nw = min(max((int)rintf(ww), 0), NDIM - 1);
    const int lv = __ldg(&lab[VIDX(nd, nh, nw)]);

    const float4 v000 = __ldg(&img[VIDX(d0, h0, w0)]);
    const float4 v001 = __ldg(&img[VIDX(d0, h0, w1)]);
    const float4 v010 = __ldg(&img[VIDX(d0, h1, w0)]);
    const float4 v011 = __ldg(&img[VIDX(d0, h1, w1)]);
    const float4 v100 = __ldg(&img[VIDX(d1, h0, w0)]);
    const float4 v101 = __ldg(&img[VIDX(d1, h0, w1)]);
    const float4 v110 = __ldg(&img[VIDX(d1, h1, w0)]);
    const float4 v111 = __ldg(&img[VIDX(d1, h1, w1)]);

    const float omw = 1.0f - tw, omh = 1.0f - th_, omd = 1.0f - td;

    float4 c00, c01, c10, c11, c0, c1, res;
    c00.x = v000.x * omw + v001.x * tw;  c00.y = v000.y * omw + v001.y * tw;
    c00.z = v000.z * omw + v001.z * tw;  c00.w = v000.w * omw + v001.w * tw;
    c01.x = v010.x * omw + v011.x * tw;  c01.y = v010.y * omw + v011.y * tw;
    c01.z = v010.z * omw + v011.z * tw;  c01.w = v010.w * omw + v011.w * tw;
    c10.x = v100.x * omw + v101.x * tw;  c10.y = v100.y * omw + v101.y * tw;
    c10.z = v100.z * omw + v101.z * tw;  c10.w = v100.w * omw + v101.w * tw;
    c11.x = v110.x * omw + v111.x * tw;  c11.y = v110.y * omw + v111.y * tw;
    c11.z = v110.z * omw + v111.z * tw;  c11.w = v110.w * omw + v111.w * tw;

    c0.x = c00.x * omh + c01.x * th_;  c0.y = c00.y * omh + c01.y * th_;
    c0.z = c00.z * omh + c01.z * th_;  c0.w = c00.w * omh + c01.w * th_;
    c1.x = c10.x * omh + c11.x * th_;  c1.y = c10.y * omh + c11.y * th_;
    c1.z = c10.z * omh + c11.z * th_;  c1.w = c10.w * omh + c11.w * th_;

    res.x = c0.x * omd + c1.x * td;  res.y = c0.y * omd + c1.y * td;
    res.z = c0.z * omd + c1.z * td;  res.w = c0.w * omd + c1.w * td;

    const int lin = VIDX(d, h, w);
    reinterpret_cast<float4*>(out)[lin] = res;
    out[IMG_ELEMS + lin] = (float)lv;
    #undef VIDX
}

// ---------------------------------------------------------------------------
// kernel_launch — graph-capturable, allocation-free
// ---------------------------------------------------------------------------
extern "C" void kernel_launch(void* const* d_in, const int* in_sizes, int n_in,
                              void* d_out, int out_size) {
    const float4* img    = (const float4*)d_in[0];  // image_volume [2,128,128,128,4] f32
    const int*    lab    = (const int*)d_in[1];     // label_volume [2,128,128,128,1] i32
    const float*  coarse = (const float*)d_in[2];   // coarse_flow  [2,4,4,4,3] f32
    float*        out    = (float*)d_out;

    build_M_kernel<<<NDIM, 64>>>();
    build_T2_kernel<<<dim3(NDIM, NB), NDIM>>>(coarse);
    warp_kernel<<<dim3(NDIM / 2, NDIM, NB), dim3(NDIM, 2)>>>(img, lab, out);
}